// round 8
// baseline (speedup 1.0000x reference)
#include <cuda_runtime.h>

#define TPB   256
#define ROWS  64         // batch rows per CTA
#define RPT   8          // rows per warp (lane-distributed units, warp-shared rows)

typedef unsigned int u32;
typedef unsigned long long ull;

// ---------- packed f32x2 helpers ----------
__device__ __forceinline__ ull pack2(float lo, float hi) {
    ull r; asm("mov.b64 %0, {%1, %2};" : "=l"(r) : "f"(lo), "f"(hi)); return r;
}
__device__ __forceinline__ void unpack2(ull v, float& lo, float& hi) {
    asm("mov.b64 {%0, %1}, %2;" : "=f"(lo), "=f"(hi) : "l"(v));
}
__device__ __forceinline__ ull ffma2(ull a, ull b, ull c) {
    ull d; asm("fma.rn.f32x2 %0, %1, %2, %3;" : "=l"(d) : "l"(a), "l"(b), "l"(c)); return d;
}

// ---------- HW tanh (1 MUFU op) ----------
__device__ __forceinline__ float tanh_hw(float x) {
    float y; asm("tanh.approx.f32 %0, %1;" : "=f"(y) : "f"(x)); return y;
}
__device__ __forceinline__ float sigm(float x) {       // sigma(x) = 0.5 + 0.5*tanh(x/2)
    return fmaf(0.5f, tanh_hw(0.5f * x), 0.5f);
}

// SMEM (floats): sU[64][256] | sW[256] | sB[256] | sWd[64] | sX[ROWS*5]
#define OFF_U   0
#define OFF_W   16384
#define OFF_B   (OFF_W + 256)
#define OFF_WD  (OFF_B + 256)
#define OFF_X   (OFF_WD + 64)
#define SMEM_FLOATS (OFF_X + ROWS*5)     // 17280 floats = 69120 B -> 2 CTAs/SM

// One k-step of the register GEMM: av pairs come from lane (k&31)'s hp[] via shfl.
#define GEMM_K(kidx, P0, P1, P2, P3)                                           \
    {                                                                          \
        const ull a0 = __shfl_sync(0xFFFFFFFFu, (P0), (kidx));                 \
        const ull a1 = __shfl_sync(0xFFFFFFFFu, (P1), (kidx));                 \
        const ull a2 = __shfl_sync(0xFFFFFFFFu, (P2), (kidx));                 \
        const ull a3 = __shfl_sync(0xFFFFFFFFu, (P3), (kidx));                 \
        ull bv[8];                                                             \
        _Pragma("unroll")                                                      \
        for (int g = 0; g < 4; ++g) {                                          \
            const float b0 = Bk[g * 64];                                       \
            const float b1 = Bk[g * 64 + 32];                                  \
            bv[g * 2 + 0] = pack2(b0, b0);                                     \
            bv[g * 2 + 1] = pack2(b1, b1);                                     \
        }                                                                      \
        _Pragma("unroll")                                                      \
        for (int cs = 0; cs < 8; ++cs) {                                       \
            acc[0 * 8 + cs] = ffma2(a0, bv[cs], acc[0 * 8 + cs]);              \
            acc[1 * 8 + cs] = ffma2(a1, bv[cs], acc[1 * 8 + cs]);              \
            acc[2 * 8 + cs] = ffma2(a2, bv[cs], acc[2 * 8 + cs]);              \
            acc[3 * 8 + cs] = ffma2(a3, bv[cs], acc[3 * 8 + cs]);              \
        }                                                                      \
    }

__global__ void __launch_bounds__(TPB, 2)
lstm_reg(const float* __restrict__ x, const float* __restrict__ W,
         const float* __restrict__ U, const float* __restrict__ b,
         const float* __restrict__ Wd, const float* __restrict__ bd,
         float* __restrict__ out, int Bn)
{
    extern __shared__ float sm[];
    float* sU  = sm + OFF_U;
    float* sW  = sm + OFF_W;
    float* sB  = sm + OFF_B;
    float* sWd = sm + OFF_WD;
    float* sX  = sm + OFF_X;

    const int tid = threadIdx.x;
    const int cx  = tid & 31;        // lane: owns units {cx, cx+32}
    const int ry  = tid >> 5;        // warp: owns rows [ry*8, ry*8+8)
    const int r0  = ry * RPT;
    const long rowBase = (long)blockIdx.x * ROWS;

    // ---- stage weights + this CTA's x slice ----
    {
        const float4* Us = (const float4*)U;
        float4* Ud = (float4*)sU;
#pragma unroll
        for (int i = 0; i < 16; ++i) Ud[tid + i * TPB] = Us[tid + i * TPB];
        sW[tid] = W[tid];
        sB[tid] = b[tid];
        if (tid < 64) sWd[tid] = Wd[tid];
        const float* xs = x + rowBase * 5;
        for (int i = tid; i < ROWS * 5; i += TPB)
            if (rowBase * 5 + i < (long)Bn * 5) sX[i] = xs[i];
    }
    __syncthreads();                 // only CTA-wide sync in the kernel

    float c[RPT * 2];                // c-state: [row][unit]
#pragma unroll
    for (int i = 0; i < RPT * 2; ++i) c[i] = 0.f;

    ull hp[8];                       // h fragment: hp[uh*4+j] = (h[cx+32uh][2j], h[.][2j+1])
    float part[RPT];                 // dense partials (t==4)

#pragma unroll 1
    for (int t = 0; t < 5; ++t) {
        ull acc[32];                 // z tile: 4 row-pairs x 8 cols (4 gates x 2 units)
#pragma unroll
        for (int i = 0; i < 32; ++i) acc[i] = 0ull;

        if (t > 0) {
            const float* Bp = sU + cx;
            // half 0: units k = 0..31 (source fragment hp[0..3])
#pragma unroll 8
            for (int k = 0; k < 32; ++k) {
                const float* Bk = Bp + k * 256;
                GEMM_K(k, hp[0], hp[1], hp[2], hp[3]);
            }
            // half 1: units k = 32..63 (source fragment hp[4..7])
#pragma unroll 8
            for (int k = 0; k < 32; ++k) {
                const float* Bk = Bp + (k + 32) * 256;
                GEMM_K(k, hp[4], hp[5], hp[6], hp[7]);
            }
        }

        // ---- epilogue: z = acc + x*W + b -> gates -> c/h in registers ----
        const bool last = (t == 4);
#pragma unroll
        for (int rp = 0; rp < 4; ++rp) {
            float z0[8], z1[8];
#pragma unroll
            for (int cs = 0; cs < 8; ++cs) unpack2(acc[rp * 8 + cs], z0[cs], z1[cs]);
            float lo[2];             // h of row 2rp for uh=0,1 (await pairing)
#pragma unroll
            for (int h2 = 0; h2 < 2; ++h2) {
                const int r = 2 * rp + h2;
                const float xr = sX[(r0 + r) * 5 + t];
                const float* zz = h2 ? z1 : z0;
#pragma unroll
                for (int uh = 0; uh < 2; ++uh) {
                    const int u = cx + uh * 32;
                    const float zi = zz[0 + uh] + fmaf(xr, sW[u],       sB[u]);
                    const float zf = zz[2 + uh] + fmaf(xr, sW[64 + u],  sB[64 + u]);
                    const float zg = zz[4 + uh] + fmaf(xr, sW[128 + u], sB[128 + u]);
                    const float zo = zz[6 + uh] + fmaf(xr, sW[192 + u], sB[192 + u]);
                    const float ig = sigm(zi), fg = sigm(zf);
                    const float gg = tanh_hw(zg), og = sigm(zo);
                    const float cn = fmaf(fg, c[r * 2 + uh], ig * gg);
                    c[r * 2 + uh] = cn;
                    const float h = og * tanh_hw(cn);
                    if (last) {
                        if (uh == 0) part[r] = h * sWd[cx];
                        else         part[r] = fmaf(h, sWd[cx + 32], part[r]);
                    } else {
                        if (h2 == 0) lo[uh] = h;                  // row 2rp
                        else         hp[uh * 4 + rp] = pack2(lo[uh], h);  // + row 2rp+1
                    }
                }
            }
        }

        if (last) {
            // Dense(1, relu): reduce over units = over the 32 lanes of this warp
#pragma unroll
            for (int r = 0; r < RPT; ++r) {
#pragma unroll
                for (int s = 16; s; s >>= 1)
                    part[r] += __shfl_xor_sync(0xFFFFFFFFu, part[r], s);
            }
            if (cx == 0) {
                const float bdv = __ldg(bd);
#pragma unroll
                for (int r = 0; r < RPT; ++r) {
                    const long orow = rowBase + r0 + r;
                    if (orow < Bn) out[orow] = fmaxf(part[r] + bdv, 0.f);
                }
            }
        }
    }
}

extern "C" void kernel_launch(void* const* d_in, const int* in_sizes, int n_in,
                              void* d_out, int out_size) {
    const float* x  = (const float*)d_in[0];
    const float* W  = (const float*)d_in[1];
    const float* U  = (const float*)d_in[2];
    const float* b  = (const float*)d_in[3];
    const float* Wd = (const float*)d_in[4];
    const float* bd = (const float*)d_in[5];
    float* out = (float*)d_out;

    const int Bn = in_sizes[0] / 5;                           // x is [B, 5, 1]
    const int smem_bytes = SMEM_FLOATS * (int)sizeof(float);  // 69120 B -> 2 CTAs/SM

    cudaFuncSetAttribute(lstm_reg, cudaFuncAttributeMaxDynamicSharedMemorySize,
                         smem_bytes);

    const int grid = (Bn + ROWS - 1) / ROWS;
    lstm_reg<<<grid, TPB, smem_bytes>>>(x, W, U, b, Wd, bd, out, Bn);
}

// round 10
// speedup vs baseline: 1.0857x; 1.0857x over previous
#include <cuda_runtime.h>

#define TPB   256
#define ROWS  64         // batch rows per CTA
#define RPT   8          // rows per warp
#define HSTR  66         // floats per unit-row of H: 64 rows + 2 pad (8B-aligned rows, 2-way STS)

typedef unsigned int u32;
typedef unsigned long long ull;

// ---------- packed f32x2 helpers ----------
__device__ __forceinline__ ull pack2(float lo, float hi) {
    ull r; asm("mov.b64 %0, {%1, %2};" : "=l"(r) : "f"(lo), "f"(hi)); return r;
}
__device__ __forceinline__ void unpack2(ull v, float& lo, float& hi) {
    asm("mov.b64 {%0, %1}, %2;" : "=f"(lo), "=f"(hi) : "l"(v));
}
__device__ __forceinline__ ull ffma2(ull a, ull b, ull c) {
    ull d; asm("fma.rn.f32x2 %0, %1, %2, %3;" : "=l"(d) : "l"(a), "l"(b), "l"(c)); return d;
}

// ---------- HW tanh (1 MUFU op) ----------
__device__ __forceinline__ float tanh_hw(float x) {
    float y; asm("tanh.approx.f32 %0, %1;" : "=f"(y) : "f"(x)); return y;
}
__device__ __forceinline__ float sigm(float x) {       // sigma(x) = 0.5 + 0.5*tanh(x/2)
    return fmaf(0.5f, tanh_hw(0.5f * x), 0.5f);
}

// SMEM (floats): sU[64][256] | sH[2][64*HSTR] | sW[256] | sB[256] | sWd[64] | sX[ROWS*5]
#define OFF_U   0
#define OFF_H0  16384
#define OFF_H1  (OFF_H0 + 64*HSTR)
#define OFF_W   (OFF_H0 + 2*64*HSTR)
#define OFF_B   (OFF_W + 256)
#define OFF_WD  (OFF_B + 256)
#define OFF_X   (OFF_WD + 64)
#define SMEM_FLOATS (OFF_X + ROWS*5)        // 25728 floats = 102912 B -> 2 CTAs/SM

__global__ void __launch_bounds__(TPB, 2)
lstm_gemm(const float* __restrict__ x, const float* __restrict__ W,
          const float* __restrict__ U, const float* __restrict__ b,
          const float* __restrict__ Wd, const float* __restrict__ bd,
          float* __restrict__ out, int Bn)
{
    extern __shared__ float sm[];
    float* sU  = sm + OFF_U;
    float* sW  = sm + OFF_W;
    float* sB  = sm + OFF_B;
    float* sWd = sm + OFF_WD;
    float* sX  = sm + OFF_X;

    const int tid = threadIdx.x;
    const int cx  = tid & 31;       // lane: owns units {cx, cx+32}
    const int ry  = tid >> 5;       // warp: owns rows [ry*8, ry*8+8)
    const int r0  = ry * RPT;
    const long rowBase = (long)blockIdx.x * ROWS;

    // ---- stage weights + this CTA's x slice ----
    {
        const float4* Us = (const float4*)U;
        float4* Ud = (float4*)sU;
#pragma unroll
        for (int i = 0; i < 16; ++i) Ud[tid + i * TPB] = Us[tid + i * TPB];
        sW[tid] = W[tid];
        sB[tid] = b[tid];
        if (tid < 64) sWd[tid] = Wd[tid];
        const float* xs = x + rowBase * 5;
        for (int i = tid; i < ROWS * 5; i += TPB)
            if (rowBase * 5 + i < (long)Bn * 5) sX[i] = xs[i];
    }
    __syncthreads();     // staging barrier (only CTA-wide sync)

    // Hoist input weights: 8 regs (4 gates x 2 units), order matches acc cols
    float wr[8];
#pragma unroll
    for (int g = 0; g < 4; ++g) {
        wr[g * 2 + 0] = sW[g * 64 + cx];
        wr[g * 2 + 1] = sW[g * 64 + cx + 32];
    }

    float c[RPT * 2];               // c-state: [row][unit]
#pragma unroll
    for (int i = 0; i < RPT * 2; ++i) c[i] = 0.f;

    float part[RPT];                // dense partials (t==4)

#pragma unroll 1
    for (int t = 0; t < 5; ++t) {
        // acc init = bias (folds +b into the GEMM accumulator)
        ull acc[32];
        {
            ull binit[8];
#pragma unroll
            for (int g = 0; g < 4; ++g) {
                const float b0 = sB[g * 64 + cx];
                const float b1 = sB[g * 64 + cx + 32];
                binit[g * 2 + 0] = pack2(b0, b0);
                binit[g * 2 + 1] = pack2(b1, b1);
            }
#pragma unroll
            for (int rp = 0; rp < 4; ++rp)
#pragma unroll
                for (int cs = 0; cs < 8; ++cs) acc[rp * 8 + cs] = binit[cs];
        }

        if (t > 0) {
            const float* Hc = sm + (((t - 1) & 1) ? OFF_H1 : OFF_H0);
            const float* Ap = Hc + r0;          // H[k][row], this warp's 8 rows
            const float* Bp = sU + cx;
#pragma unroll 8
            for (int k = 0; k < 64; ++k) {
                // av: 4x LDS.64 broadcast (rows are 8B-aligned; NOT 16B -> no float4)
                ull av[4];
#pragma unroll
                for (int j = 0; j < 4; ++j) {
                    float2 a2 = *(const float2*)(Ap + k * HSTR + 2 * j);
                    av[j] = pack2(a2.x, a2.y);
                }
                ull bv[8];                       // 8 U cols (stride-1 LDS, conflict-free)
#pragma unroll
                for (int g = 0; g < 4; ++g) {
                    const float b0 = Bp[k * 256 + g * 64];
                    const float b1 = Bp[k * 256 + g * 64 + 32];
                    bv[g * 2 + 0] = pack2(b0, b0);
                    bv[g * 2 + 1] = pack2(b1, b1);
                }
#pragma unroll
                for (int rp = 0; rp < 4; ++rp)
#pragma unroll
                    for (int cs = 0; cs < 8; ++cs)
                        acc[rp * 8 + cs] = ffma2(av[rp], bv[cs], acc[rp * 8 + cs]);
            }
        }

        // ---- epilogue: z = acc(+b) + x*Wreg, gates, c/h update ----
        float* Hn = sm + ((t & 1) ? OFF_H1 : OFF_H0);
        const bool last = (t == 4);

#pragma unroll
        for (int rp = 0; rp < 4; ++rp) {
            float z0[8], z1[8];
#pragma unroll
            for (int cs = 0; cs < 8; ++cs) unpack2(acc[rp * 8 + cs], z0[cs], z1[cs]);
#pragma unroll
            for (int h2 = 0; h2 < 2; ++h2) {
                const int r = 2 * rp + h2;
                const float xr = sX[(r0 + r) * 5 + t];   // warp-uniform broadcast
                const float* zz = h2 ? z1 : z0;
#pragma unroll
                for (int uh = 0; uh < 2; ++uh) {
                    const float zi = fmaf(xr, wr[0 + uh], zz[0 + uh]);
                    const float zf = fmaf(xr, wr[2 + uh], zz[2 + uh]);
                    const float zg = fmaf(xr, wr[4 + uh], zz[4 + uh]);
                    const float zo = fmaf(xr, wr[6 + uh], zz[6 + uh]);
                    const float ig = sigm(zi), fg = sigm(zf);
                    const float gg = tanh_hw(zg), og = sigm(zo);
                    const float cn = fmaf(fg, c[r * 2 + uh], ig * gg);
                    c[r * 2 + uh] = cn;
                    const float h = og * tanh_hw(cn);
                    if (!last) {
                        Hn[(cx + uh * 32) * HSTR + r0 + r] = h;   // 2-way STS max
                    } else {
                        if (uh == 0) part[r] = h * sWd[cx];
                        else         part[r] = fmaf(h, sWd[cx + 32], part[r]);
                    }
                }
            }
        }

        if (!last) {
            __syncwarp(0xFFFFFFFFu);   // H rows are warp-private
        } else {
            // Dense(1, relu): reduce over the 32 unit-lanes of this warp
#pragma unroll
            for (int r = 0; r < RPT; ++r) {
#pragma unroll
                for (int s = 16; s; s >>= 1)
                    part[r] += __shfl_xor_sync(0xFFFFFFFFu, part[r], s);
            }
            if (cx == 0) {
                const float bdv = __ldg(bd);
#pragma unroll
                for (int r = 0; r < RPT; ++r) {
                    const long orow = rowBase + r0 + r;
                    if (orow < Bn) out[orow] = fmaxf(part[r] + bdv, 0.f);
                }
            }
        }
    }
}

extern "C" void kernel_launch(void* const* d_in, const int* in_sizes, int n_in,
                              void* d_out, int out_size) {
    const float* x  = (const float*)d_in[0];
    const float* W  = (const float*)d_in[1];
    const float* U  = (const float*)d_in[2];
    const float* b  = (const float*)d_in[3];
    const float* Wd = (const float*)d_in[4];
    const float* bd = (const float*)d_in[5];
    float* out = (float*)d_out;

    const int Bn = in_sizes[0] / 5;                           // x is [B, 5, 1]
    const int smem_bytes = SMEM_FLOATS * (int)sizeof(float);  // 102912 B -> 2 CTAs/SM

    cudaFuncSetAttribute(lstm_gemm, cudaFuncAttributeMaxDynamicSharedMemorySize,
                         smem_bytes);

    const int grid = (Bn + ROWS - 1) / ROWS;
    lstm_gemm<<<grid, TPB, smem_bytes>>>(x, W, U, b, Wd, bd, out, Bn);
}

// round 11
// speedup vs baseline: 2.2984x; 2.1171x over previous
#include <cuda_runtime.h>
#include <cuda_bf16.h>

#define TPB   256
#define ROWS  64          // batch rows per CTA
#define HSTRB 144         // bytes per H row (72 bf16): (4*gid+tg)%32 conflict-free

typedef unsigned int u32;

// ---------- helpers ----------
__device__ __forceinline__ unsigned short f2bf(float f) {
    unsigned short u; asm("cvt.rn.bf16.f32 %0, %1;" : "=h"(u) : "f"(f)); return u;
}
__device__ __forceinline__ float bf2f(unsigned short u) { return __uint_as_float((u32)u << 16); }
__device__ __forceinline__ u32 packbf(unsigned short lo, unsigned short hi) {
    return (u32)lo | ((u32)hi << 16);
}
__device__ __forceinline__ float tanh_hw(float x) {
    float y; asm("tanh.approx.f32 %0, %1;" : "=f"(y) : "f"(x)); return y;
}
__device__ __forceinline__ float sigm(float x) {   // sigma(x) = 0.5 + 0.5*tanh(x/2)
    return fmaf(0.5f, tanh_hw(0.5f * x), 0.5f);
}
// m16n8k16 bf16 MMA, f32 accum (HMMA fallback path on sm_103)
__device__ __forceinline__ void mma16816(float* d, u32 a0, u32 a1, u32 a2, u32 a3,
                                         u32 b0, u32 b1) {
    asm volatile("mma.sync.aligned.m16n8k16.row.col.f32.bf16.bf16.f32 "
                 "{%0,%1,%2,%3}, {%4,%5,%6,%7}, {%8,%9}, {%0,%1,%2,%3};"
                 : "+f"(d[0]), "+f"(d[1]), "+f"(d[2]), "+f"(d[3])
                 : "r"(a0), "r"(a1), "r"(a2), "r"(a3), "r"(b0), "r"(b1));
}

// SMEM byte offsets
#define OFF_UF   0                       // frag-linear U (hi+lo): 32N x 4kt x 32 lanes x 16B = 65536
#define OFF_HH0  65536                   // H hi, buf0: 64 x 144 = 9216
#define OFF_HL0  (OFF_HH0 +  9216)       // H lo, buf0
#define OFF_HH1  (OFF_HH0 + 18432)       // H hi, buf1
#define OFF_HL1  (OFF_HH0 + 27648)       // H lo, buf1
#define OFF_SW   (OFF_HH0 + 36864)       // W[256] f32
#define OFF_SB   (OFF_SW + 1024)         // b[256] f32
#define OFF_SWD  (OFF_SB + 1024)         // Wd[64] f32
#define OFF_SX   (OFF_SWD + 256)         // x[64*5] f32
#define SMEM_BYTES (OFF_SX + 1280)       // 105984 B -> 2 CTAs/SM

__global__ void __launch_bounds__(TPB, 2)
lstm_mma(const float* __restrict__ x, const float* __restrict__ W,
         const float* __restrict__ U, const float* __restrict__ b,
         const float* __restrict__ Wd, const float* __restrict__ bd,
         float* __restrict__ out, int Bn)
{
    extern __shared__ char smem[];
    float* sW  = (float*)(smem + OFF_SW);
    float* sB  = (float*)(smem + OFF_SB);
    float* sWd = (float*)(smem + OFF_SWD);
    float* sX  = (float*)(smem + OFF_SX);

    const int tid  = threadIdx.x;
    const int lane = tid & 31;
    const int wid  = tid >> 5;
    const int gid  = lane >> 2;          // frag group id (row / B-col index)
    const int tg   = lane & 3;           // frag thread-in-group (k / D-col index)
    const int rg   = wid >> 2;           // row-group: rows [rg*32, rg*32+32)
    const int cg   = wid & 3;            // unit-group: units [cg*16, cg*16+16)
    const long rowBase = (long)blockIdx.x * ROWS;

    // ---- stage: frag-linear U (hi/lo bf16), W, b, Wd, x ----
    for (int idx = tid; idx < 4096; idx += TPB) {
        const int N  = idx >> 7;         // global n-tile 0..31
        const int kt = (idx >> 5) & 3;   // k-tile 0..3
        const int l  = idx & 31;
        const int g2 = l >> 2, t2 = l & 3;
        const int col = N * 8 + g2;
        const int k0  = kt * 16 + 2 * t2;
        const float u0 = U[k0 * 256 + col],       u1 = U[(k0 + 1) * 256 + col];
        const float u8 = U[(k0 + 8) * 256 + col], u9 = U[(k0 + 9) * 256 + col];
        const unsigned short h0 = f2bf(u0), h1 = f2bf(u1), h8 = f2bf(u8), h9 = f2bf(u9);
        const unsigned short l0 = f2bf(u0 - bf2f(h0)), l1 = f2bf(u1 - bf2f(h1));
        const unsigned short l8 = f2bf(u8 - bf2f(h8)), l9 = f2bf(u9 - bf2f(h9));
        uint4 v;
        v.x = packbf(h0, h1);  v.y = packbf(h8, h9);   // B_hi regs
        v.z = packbf(l0, l1);  v.w = packbf(l8, l9);   // B_lo regs
        *(uint4*)(smem + OFF_UF + idx * 16) = v;
    }
    sW[tid] = W[tid];
    sB[tid] = b[tid];
    if (tid < 64) sWd[tid] = Wd[tid];
    {
        const float* xs = x + rowBase * 5;
        for (int i = tid; i < ROWS * 5; i += TPB)
            if (rowBase * 5 + i < (long)Bn * 5) sX[i] = xs[i];
    }
    __syncthreads();

    float c[16];                         // c-state: [mi][h][j][e]
#pragma unroll
    for (int i = 0; i < 16; ++i) c[i] = 0.f;
    float pd[4];                         // dense partials per (mi,h) row
#pragma unroll
    for (int i = 0; i < 4; ++i) pd[i] = 0.f;

#pragma unroll 1
    for (int t = 0; t < 5; ++t) {
        // ---- acc init: z = x*W + b (per D-frag cell) ----
        float acc[2][4][2][4];           // [mi][gate][j][2h+e]
#pragma unroll
        for (int mi = 0; mi < 2; ++mi) {
            const int row0 = rg * 32 + mi * 16 + gid;
            const float xr0 = sX[row0 * 5 + t];
            const float xr1 = sX[(row0 + 8) * 5 + t];
#pragma unroll
            for (int ga = 0; ga < 4; ++ga)
#pragma unroll
                for (int j = 0; j < 2; ++j) {
                    const int colb = ga * 64 + cg * 16 + 8 * j + 2 * tg;
                    const float2 w2 = *(const float2*)(sW + colb);
                    const float2 b2 = *(const float2*)(sB + colb);
                    acc[mi][ga][j][0] = fmaf(xr0, w2.x, b2.x);
                    acc[mi][ga][j][1] = fmaf(xr0, w2.y, b2.y);
                    acc[mi][ga][j][2] = fmaf(xr1, w2.x, b2.x);
                    acc[mi][ga][j][3] = fmaf(xr1, w2.y, b2.y);
                }
        }

        // ---- tensor mainloop: acc += Hhi*Uhi + Hhi*Ulo + Hlo*Uhi ----
        if (t > 0) {
            const char* HH = smem + (((t - 1) & 1) ? OFF_HH1 : OFF_HH0);
            const char* HL = smem + (((t - 1) & 1) ? OFF_HL1 : OFF_HL0);
#pragma unroll 1
            for (int kt = 0; kt < 4; ++kt) {
                u32 ah[2][4], al[2][4];
#pragma unroll
                for (int mi = 0; mi < 2; ++mi) {
                    const int off = (rg * 32 + mi * 16 + gid) * HSTRB + (kt * 16 + 2 * tg) * 2;
                    ah[mi][0] = *(const u32*)(HH + off);
                    ah[mi][1] = *(const u32*)(HH + off + 8 * HSTRB);
                    ah[mi][2] = *(const u32*)(HH + off + 16);
                    ah[mi][3] = *(const u32*)(HH + off + 8 * HSTRB + 16);
                    al[mi][0] = *(const u32*)(HL + off);
                    al[mi][1] = *(const u32*)(HL + off + 8 * HSTRB);
                    al[mi][2] = *(const u32*)(HL + off + 16);
                    al[mi][3] = *(const u32*)(HL + off + 8 * HSTRB + 16);
                }
#pragma unroll
                for (int ga = 0; ga < 4; ++ga)
#pragma unroll
                    for (int j = 0; j < 2; ++j) {
                        const int N = 8 * ga + 2 * cg + j;
                        const uint4 bf = *(const uint4*)(smem + OFF_UF + ((N * 4 + kt) * 32 + lane) * 16);
#pragma unroll
                        for (int mi = 0; mi < 2; ++mi) {
                            mma16816(acc[mi][ga][j], ah[mi][0], ah[mi][1], ah[mi][2], ah[mi][3], bf.x, bf.y);
                            mma16816(acc[mi][ga][j], ah[mi][0], ah[mi][1], ah[mi][2], ah[mi][3], bf.z, bf.w);
                            mma16816(acc[mi][ga][j], al[mi][0], al[mi][1], al[mi][2], al[mi][3], bf.x, bf.y);
                        }
                    }
            }
        }

        // ---- epilogue: gates -> c,h; h -> bf16 hi/lo into H(t&1) ----
        const bool last = (t == 4);
        char* HHn = smem + ((t & 1) ? OFF_HH1 : OFF_HH0);
        char* HLn = smem + ((t & 1) ? OFF_HL1 : OFF_HL0);

#pragma unroll
        for (int mi = 0; mi < 2; ++mi)
#pragma unroll
            for (int h = 0; h < 2; ++h) {
                const int row = rg * 32 + mi * 16 + gid + 8 * h;
#pragma unroll
                for (int j = 0; j < 2; ++j) {
                    const int ub = cg * 16 + 8 * j + 2 * tg;
                    float hv[2];
#pragma unroll
                    for (int e = 0; e < 2; ++e) {
                        const int ix = 2 * h + e;
                        const float zi = acc[mi][0][j][ix];
                        const float zf = acc[mi][1][j][ix];
                        const float zg = acc[mi][2][j][ix];
                        const float zo = acc[mi][3][j][ix];
                        const float ig = sigm(zi), fg = sigm(zf);
                        const float gg = tanh_hw(zg), og = sigm(zo);
                        const int cid = mi * 8 + h * 4 + j * 2 + e;
                        const float cn = fmaf(fg, c[cid], ig * gg);
                        c[cid] = cn;
                        hv[e] = og * tanh_hw(cn);
                    }
                    if (!last) {
                        const unsigned short h0 = f2bf(hv[0]), h1 = f2bf(hv[1]);
                        const unsigned short l0 = f2bf(hv[0] - bf2f(h0));
                        const unsigned short l1 = f2bf(hv[1] - bf2f(h1));
                        *(u32*)(HHn + row * HSTRB + ub * 2) = packbf(h0, h1);
                        *(u32*)(HLn + row * HSTRB + ub * 2) = packbf(l0, l1);
                    } else {
                        const float2 wd2 = *(const float2*)(sWd + ub);
                        pd[mi * 2 + h] = fmaf(hv[0], wd2.x, fmaf(hv[1], wd2.y, pd[mi * 2 + h]));
                    }
                }
            }

        if (!last) {
            // sync only the 4 warps sharing this row-group's H rows
            asm volatile("bar.sync %0, 128;" :: "r"(rg + 1) : "memory");
        }
    }

    // ---- Dense(1, relu): scratch reduce over 16 (cg,tg) slots per row ----
    float* scr = (float*)(smem + OFF_HH0);      // H buf0 region is free at t=4
#pragma unroll
    for (int mi = 0; mi < 2; ++mi)
#pragma unroll
        for (int h = 0; h < 2; ++h) {
            const int row = rg * 32 + mi * 16 + gid + 8 * h;
            scr[row * 16 + cg * 4 + tg] = pd[mi * 2 + h];
        }
    __syncthreads();
    if (tid < ROWS) {
        float s = 0.f;
#pragma unroll
        for (int k = 0; k < 16; ++k) s += scr[tid * 16 + k];
        const long orow = rowBase + tid;
        if (orow < Bn) out[orow] = fmaxf(s + __ldg(bd), 0.f);
    }
}

extern "C" void kernel_launch(void* const* d_in, const int* in_sizes, int n_in,
                              void* d_out, int out_size) {
    const float* x  = (const float*)d_in[0];
    const float* W  = (const float*)d_in[1];
    const float* U  = (const float*)d_in[2];
    const float* b  = (const float*)d_in[3];
    const float* Wd = (const float*)d_in[4];
    const float* bd = (const float*)d_in[5];
    float* out = (float*)d_out;

    const int Bn = in_sizes[0] / 5;      // x is [B, 5, 1]
    cudaFuncSetAttribute(lstm_mma, cudaFuncAttributeMaxDynamicSharedMemorySize, SMEM_BYTES);

    const int grid = (Bn + ROWS - 1) / ROWS;
    lstm_mma<<<grid, TPB, SMEM_BYTES>>>(x, W, U, b, Wd, bd, out, Bn);
}